// round 5
// baseline (speedup 1.0000x reference)
#include <cuda_runtime.h>

// RateBasedNeuron: N=2^23 neuron sim, fully parallel formulation.
//  rate[t] = a*rate[t-1] + alpha*I[t]  (a = 1-1/tau, contractive)
//  p[t] = clip(rate/thr,0,1)*0.1 ; 3-state refractory DFA -> spikes.
//
// Per-block 512-step halo (a^512*50 ~ 2e-10) makes blocks independent; the
// halo also warms up the refractory DFA (state collapses after any 2
// consecutive non-fire steps). v4: NO shared-memory data staging. Each
// thread owns 32 consecutive elements; all global access is blocked
// LDG.128/STG.128 (every sector fully consumed -> DRAM-efficient, MLP=8).
// b stays in registers between passes. Smem = 3 tiny warp-aggregate arrays.

#define THREADS 256
#define ITEMS   32
#define REGION  (THREADS * ITEMS)    // 8192
#define HALO    512
#define TILE    (REGION - HALO)      // 7680
#define FULLMASK 0xffffffffu
#define IDMAP   0x00020100u          // identity state map bytes [0,1,2]

__global__ void __launch_bounds__(THREADS, 4)
neuron_kernel(const float* __restrict__ gI, const float* __restrict__ gU,
              const float* __restrict__ gTau, const float* __restrict__ gThr,
              float* __restrict__ gOut, int N)
{
    __shared__ float    wA[8];
    __shared__ float    wB[8];
    __shared__ unsigned wS[8];

    const int tid  = threadIdx.x;
    const int lane = tid & 31;
    const int wid  = tid >> 5;

    const float alpha = __fdiv_rn(1.0f, gTau[0]);
    const float thr   = gThr[0];
    const float a = 1.0f - alpha;

    const long long base = (long long)blockIdx.x * TILE - HALO;
    const long long g0   = base + (long long)tid * ITEMS;  // 128B aligned
    const bool intLoad = (base >= 1) && (base + REGION <= (long long)N);

    // ---- Load this thread's 32 b-values (alpha*I) into registers ----
    float4 b4[8];
    if (intLoad) {
        const float4* pI = (const float4*)(gI + g0);
        #pragma unroll
        for (int c = 0; c < 8; c++) {
            float4 v = pI[c];
            v.x *= alpha; v.y *= alpha; v.z *= alpha; v.w *= alpha;
            b4[c] = v;
        }
    } else {
        #pragma unroll
        for (int c = 0; c < 8; c++) {
            long long g = g0 + 4 * c;
            float4 v;
            v.x = (g + 0 >= 1 && g + 0 < (long long)N) ? alpha * gI[g + 0] : 0.0f;
            v.y = (g + 1 >= 1 && g + 1 < (long long)N) ? alpha * gI[g + 1] : 0.0f;
            v.z = (g + 2 >= 1 && g + 2 < (long long)N) ? alpha * gI[g + 2] : 0.0f;
            v.w = (g + 3 >= 1 && g + 3 < (long long)N) ? alpha * gI[g + 3] : 0.0f;
            b4[c] = v;
        }
    }

    // ---- Pass 1: thread-local affine reduce (r -> A*r + B, r_in = 0) ----
    float B = 0.0f;
    #pragma unroll
    for (int c = 0; c < 8; c++) {
        B = fmaf(a, B, b4[c].x); B = fmaf(a, B, b4[c].y);
        B = fmaf(a, B, b4[c].z); B = fmaf(a, B, b4[c].w);
    }
    float a2 = a * a, a4 = a2 * a2, a8 = a4 * a4, a16 = a8 * a8;
    float A = a16 * a16;                 // a^32

    // ---- Intra-warp inclusive shuffle scan of affine maps ----
    float Ai = A, Bi = B;
    #pragma unroll
    for (int d = 1; d < 32; d <<= 1) {
        float Au = __shfl_up_sync(FULLMASK, Ai, d);
        float Bu = __shfl_up_sync(FULLMASK, Bi, d);
        if (lane >= d) { Bi = fmaf(Bu, Ai, Bi); Ai *= Au; }
    }
    if (lane == 31) { wA[wid] = Ai; wB[wid] = Bi; }
    __syncthreads();

    // Warp-prefix affine (r0 = 0), then exclusive per-thread prefix
    float Bp = 0.0f;
    #pragma unroll
    for (int w = 0; w < 7; w++)
        if (w < wid) Bp = fmaf(wA[w], Bp, wB[w]);
    float Aprev = __shfl_up_sync(FULLMASK, Ai, 1);
    float Bprev = __shfl_up_sync(FULLMASK, Bi, 1);
    float rin = (lane == 0) ? Bp : fmaf(Aprev, Bp, Bprev);

    // ---- Pass 2: finalize rates, load u blocked, build eligibility bits ----
    const float4* pU = (const float4*)(gU + g0);
    float r = rin;
    unsigned e = 0;
    #pragma unroll
    for (int c = 0; c < 8; c++) {
        float4 u4;
        if (intLoad) {
            u4 = pU[c];
        } else {
            long long g = g0 + 4 * c;
            u4.x = (g + 0 >= 0 && g + 0 < (long long)N) ? gU[g + 0] : 1.0f;
            u4.y = (g + 1 >= 0 && g + 1 < (long long)N) ? gU[g + 1] : 1.0f;
            u4.z = (g + 2 >= 0 && g + 2 < (long long)N) ? gU[g + 2] : 1.0f;
            u4.w = (g + 3 >= 0 && g + 3 < (long long)N) ? gU[g + 3] : 1.0f;
        }
        float q;
        r = fmaf(a, r, b4[c].x);
        q = __fdiv_rn(r, thr); q = fminf(fmaxf(q, 0.0f), 1.0f) * 0.1f;
        e |= (u4.x < q ? 1u : 0u) << (4 * c + 0);
        r = fmaf(a, r, b4[c].y);
        q = __fdiv_rn(r, thr); q = fminf(fmaxf(q, 0.0f), 1.0f) * 0.1f;
        e |= (u4.y < q ? 1u : 0u) << (4 * c + 1);
        r = fmaf(a, r, b4[c].z);
        q = __fdiv_rn(r, thr); q = fminf(fmaxf(q, 0.0f), 1.0f) * 0.1f;
        e |= (u4.z < q ? 1u : 0u) << (4 * c + 2);
        r = fmaf(a, r, b4[c].w);
        q = __fdiv_rn(r, thr); q = fminf(fmaxf(q, 0.0f), 1.0f) * 0.1f;
        e |= (u4.w < q ? 1u : 0u) << (4 * c + 3);
    }

    // ---- DFA: spikes + outgoing state for each incoming state s in {0,1,2} -
    unsigned spk0, spk1, spk2, fmap;
    {
        unsigned sp[3], out[3];
        #pragma unroll
        for (int s = 0; s < 3; s++) {
            unsigned es = e & ~((1u << s) - 1u);
            unsigned sk = 0;
            while (es) {
                unsigned b = es & (0u - es);           // lowest eligible fire
                sk |= b;
                es &= ~(b | (b << 1) | (b << 2));      // refractory suppression
            }
            sp[s] = sk;
            int hb = sk ? (31 - __clz(sk)) : -100;
            int o = hb + 3 - ITEMS;                    // leftover refractory
            out[s] = (o > 0) ? (unsigned)o : 0u;
        }
        spk0 = sp[0]; spk1 = sp[1]; spk2 = sp[2];
        fmap = out[0] | (out[1] << 8) | (out[2] << 16);
    }

    // ---- Intra-warp scan of state maps (compose = one __byte_perm) ----
    unsigned Fi = fmap;
    #pragma unroll
    for (int d = 1; d < 32; d <<= 1) {
        unsigned Fu = __shfl_up_sync(FULLMASK, Fi, d);
        if (lane >= d) Fi = __byte_perm(Fi, 0, Fu);
    }
    if (lane == 31) wS[wid] = Fi;
    __syncthreads();

    unsigned Sp = IDMAP;
    #pragma unroll
    for (int w = 0; w < 7; w++)
        if (w < wid) Sp = __byte_perm(wS[w], 0, Sp);
    unsigned Fprev = __shfl_up_sync(FULLMASK, Fi, 1);
    unsigned X = (lane == 0) ? Sp : __byte_perm(Fprev, 0, Sp);
    unsigned s_in = X & 3u;

    unsigned spikes = (s_in == 0) ? spk0 : ((s_in == 1) ? spk1 : spk2);

    // ---- Blocked vector store of this thread's spikes (halo threads skip) --
    if (tid >= HALO / ITEMS) {                         // tid >= 16
        if (g0 + ITEMS <= (long long)N) {
            float4* pO = (float4*)(gOut + g0);
            #pragma unroll
            for (int c = 0; c < 8; c++) {
                float4 s;
                s.x = ((spikes >> (4 * c + 0)) & 1u) ? 1.0f : 0.0f;
                s.y = ((spikes >> (4 * c + 1)) & 1u) ? 1.0f : 0.0f;
                s.z = ((spikes >> (4 * c + 2)) & 1u) ? 1.0f : 0.0f;
                s.w = ((spikes >> (4 * c + 3)) & 1u) ? 1.0f : 0.0f;
                pO[c] = s;
            }
        } else {
            #pragma unroll
            for (int j = 0; j < ITEMS; j++) {
                long long g = g0 + j;
                if (g < (long long)N)
                    gOut[g] = ((spikes >> j) & 1u) ? 1.0f : 0.0f;
            }
        }
    }
}

extern "C" void kernel_launch(void* const* d_in, const int* in_sizes, int n_in,
                              void* d_out, int out_size)
{
    const float* I   = (const float*)d_in[0];
    const float* u   = (const float*)d_in[1];
    const float* tau = (const float*)d_in[2];
    const float* thr = (const float*)d_in[3];
    float* out = (float*)d_out;
    const int N = in_sizes[0];

    const int blocks = (N + TILE - 1) / TILE;          // 1093
    neuron_kernel<<<blocks, THREADS>>>(I, u, tau, thr, out, N);
}

// round 8
// speedup vs baseline: 1.0887x; 1.0887x over previous
#include <cuda_runtime.h>

// RateBasedNeuron: N=2^23 neuron sim, warp-autonomous formulation (v6).
//  rate[t] = a*rate[t-1] + alpha*I[t]  (a = 1-1/tau, contractive)
//  p[t] = clip(rate/thr,0,1)*0.1 ; 3-state refractory DFA -> spikes.
//
// Each WARP owns an independent 3584-elem tile + 512-elem halo (a^512*50
// ~ 2e-10 << decision sensitivity; halo also warms the DFA). 32 serial
// segments of 128; per segment each lane owns one float4 (coalesced
// LDG/STG.128); IIR affine scan + DFA state-map scan over 32 lanes via
// shuffles, scalar carries between segments. No smem, no syncthreads.
//
// v6 fix: exact 3-state map composition. Maps are byte-packed
// (byte i = outgoing state for incoming state i). __byte_perm selectors are
// NIBBLES in the low 16 bits, so each compose first compresses the earlier
// map's bytes into nibble selectors: SEL(g) = (g&3)|((g>>4)&0x30)|((g>>8)&0x300),
// then h = byte_perm(f, 0, SEL(g)) giving h[i] = f[g[i]] byte-packed.
// (v5 fed byte-packed maps directly as selectors: correct only for constant
// maps -> rare wrong carries with 4-step windows.)

#define WSEG    128
#define NSEG    32
#define WREGION (WSEG * NSEG)        // 4096
#define WHALO   512
#define HSEG    (WHALO / WSEG)       // 4
#define WTILE   (WREGION - WHALO)    // 3584
#define PF      4
#define THREADS 256
#define FULLMASK 0xffffffffu

__device__ __forceinline__ unsigned dfa_spk(unsigned es, int* hb) {
    // greedy refractory fire over a 4-bit window: at most 2 fires
    unsigned b1 = es & (0u - es);
    unsigned r  = es & ~(b1 | (b1 << 1) | (b1 << 2));
    unsigned b2 = r & (0u - r);
    unsigned sk = b1 | b2;
    *hb = 31 - __clz(sk | 1u);                   // 0 when sk==0 (o<=0 then)
    return sk;
}

// compose byte-packed maps: apply g first, then f. h[i] = f[g[i]].
__device__ __forceinline__ unsigned dfa_compose(unsigned f, unsigned g) {
    unsigned sel = (g & 3u) | ((g >> 4) & 0x30u) | ((g >> 8) & 0x300u);
    return __byte_perm(f, 0, sel);
}

template <bool INTERIOR>
__device__ __forceinline__ void run_warp(
    const float* __restrict__ gI, const float* __restrict__ gU,
    float* __restrict__ gOut, long long base, long long N,
    float alpha, float a, float thr, int lane)
{
    const float a2 = a * a;
    const float a4 = a2 * a2;

    float    rcar = 0.0f;   // IIR carry (rate entering current segment)
    unsigned scar = 0u;     // DFA carry state in {0,1,2}

    const float4* pI4 = (const float4*)(gI + base) + lane;
    const float4* pU4 = (const float4*)(gU + base) + lane;
    float4*       pO4 = (float4*)(gOut + base) + lane;

    float4 qb[PF], qu[PF];
    if (INTERIOR) {
        #pragma unroll
        for (int j = 0; j < PF; j++) { qb[j] = pI4[j * 32]; qu[j] = pU4[j * 32]; }
    }

    #pragma unroll 1
    for (int g = 0; g < NSEG / PF; g++) {
        #pragma unroll
        for (int j = 0; j < PF; j++) {
            const int seg = g * PF + j;
            float4 bv, uv;
            if (INTERIOR) {
                bv = qb[j]; uv = qu[j];
                if (g < NSEG / PF - 1) {           // prefetch seg+PF
                    qb[j] = pI4[(seg + PF) * 32];
                    qu[j] = pU4[(seg + PF) * 32];
                }
            } else {
                long long gg = base + (long long)seg * WSEG + lane * 4;
                bv.x = (gg + 0 >= 1 && gg + 0 < N) ? gI[gg + 0] : 0.0f;
                bv.y = (gg + 1 >= 1 && gg + 1 < N) ? gI[gg + 1] : 0.0f;
                bv.z = (gg + 2 >= 1 && gg + 2 < N) ? gI[gg + 2] : 0.0f;
                bv.w = (gg + 3 >= 1 && gg + 3 < N) ? gI[gg + 3] : 0.0f;
                uv.x = (gg + 0 >= 0 && gg + 0 < N) ? gU[gg + 0] : 1.0f;
                uv.y = (gg + 1 >= 0 && gg + 1 < N) ? gU[gg + 1] : 1.0f;
                uv.z = (gg + 2 >= 0 && gg + 2 < N) ? gU[gg + 2] : 1.0f;
                uv.w = (gg + 3 >= 0 && gg + 3 < N) ? gU[gg + 3] : 1.0f;
            }
            const float b0 = alpha * bv.x, b1 = alpha * bv.y;
            const float b2 = alpha * bv.z, b3 = alpha * bv.w;

            // ---- lane-local affine reduce (4 elems): r -> a^4*r + B ----
            float B = b0;
            B = fmaf(B, a, b1); B = fmaf(B, a, b2); B = fmaf(B, a, b3);

            // ---- warp inclusive scan of affine maps ----
            float Ai = a4, Bi = B;
            #pragma unroll
            for (int d = 1; d < 32; d <<= 1) {
                float Au = __shfl_up_sync(FULLMASK, Ai, d);
                float Bu = __shfl_up_sync(FULLMASK, Bi, d);
                if (lane >= d) { Bi = fmaf(Bu, Ai, Bi); Ai *= Au; }
            }
            float Ae = __shfl_up_sync(FULLMASK, Ai, 1);
            float Be = __shfl_up_sync(FULLMASK, Bi, 1);
            float A31 = __shfl_sync(FULLMASK, Ai, 31);
            float B31 = __shfl_sync(FULLMASK, Bi, 31);
            float rin = (lane == 0) ? rcar : fmaf(Ae, rcar, Be);
            float rcar_next = fmaf(A31, rcar, B31);

            // ---- rates -> p -> eligibility bits (div.rn kept: bit-exact) --
            float r = rin, q;
            unsigned e = 0;
            r = fmaf(a, r, b0);
            q = __fdiv_rn(r, thr); q = fminf(fmaxf(q, 0.0f), 1.0f) * 0.1f;
            e |= (uv.x < q ? 1u : 0u);
            r = fmaf(a, r, b1);
            q = __fdiv_rn(r, thr); q = fminf(fmaxf(q, 0.0f), 1.0f) * 0.1f;
            e |= (uv.y < q ? 2u : 0u);
            r = fmaf(a, r, b2);
            q = __fdiv_rn(r, thr); q = fminf(fmaxf(q, 0.0f), 1.0f) * 0.1f;
            e |= (uv.z < q ? 4u : 0u);
            r = fmaf(a, r, b3);
            q = __fdiv_rn(r, thr); q = fminf(fmaxf(q, 0.0f), 1.0f) * 0.1f;
            e |= (uv.w < q ? 8u : 0u);
            rcar = rcar_next;

            // ---- DFA over this lane's 4 steps, per incoming state --------
            int h0, h1, h2;
            unsigned sp0 = dfa_spk(e,        &h0);
            unsigned sp1 = dfa_spk(e & ~1u,  &h1);
            unsigned sp2 = dfa_spk(e & ~3u,  &h2);
            unsigned o0 = (h0 > 1) ? (unsigned)(h0 - 1) : 0u;  // hb+3-4
            unsigned o1 = (h1 > 1) ? (unsigned)(h1 - 1) : 0u;
            unsigned o2 = (h2 > 1) ? (unsigned)(h2 - 1) : 0u;
            unsigned fmap = o0 | (o1 << 8) | (o2 << 16);       // byte-packed

            // ---- warp scan of state maps (exact compose) -----------------
            unsigned Fi = fmap;
            #pragma unroll
            for (int d = 1; d < 32; d <<= 1) {
                unsigned Fu = __shfl_up_sync(FULLMASK, Fi, d);
                if (lane >= d) Fi = dfa_compose(Fi, Fu);   // Fu earlier
            }
            unsigned Fe  = __shfl_up_sync(FULLMASK, Fi, 1);
            unsigned F31 = __shfl_sync(FULLMASK, Fi, 31);
            unsigned sin = (lane == 0) ? scar : ((Fe >> (scar << 3)) & 3u);
            scar = (F31 >> (scar << 3)) & 3u;

            unsigned spikes = (sin == 0) ? sp0 : ((sin == 1) ? sp1 : sp2);

            // ---- store (skip halo segments) ------------------------------
            if (seg >= HSEG) {
                if (INTERIOR) {
                    float4 s4;
                    s4.x = (spikes & 1u) ? 1.0f : 0.0f;
                    s4.y = (spikes & 2u) ? 1.0f : 0.0f;
                    s4.z = (spikes & 4u) ? 1.0f : 0.0f;
                    s4.w = (spikes & 8u) ? 1.0f : 0.0f;
                    pO4[seg * 32] = s4;
                } else {
                    long long gg = base + (long long)seg * WSEG + lane * 4;
                    #pragma unroll
                    for (int t = 0; t < 4; t++)
                        if (gg + t >= 0 && gg + t < N)
                            gOut[gg + t] = ((spikes >> t) & 1u) ? 1.0f : 0.0f;
                }
            }
        }
    }
}

__global__ void __launch_bounds__(THREADS)
neuron_kernel(const float* __restrict__ gI, const float* __restrict__ gU,
              const float* __restrict__ gTau, const float* __restrict__ gThr,
              float* __restrict__ gOut, int N, int nWT)
{
    const int gwarp = (int)((blockIdx.x * blockDim.x + threadIdx.x) >> 5);
    if (gwarp >= nWT) return;                       // whole-warp uniform exit
    const int lane = threadIdx.x & 31;

    const float alpha = __fdiv_rn(1.0f, gTau[0]);
    const float thr   = gThr[0];
    const float a     = 1.0f - alpha;

    const long long base = (long long)gwarp * WTILE - WHALO;
    const bool interior = (base >= 1) && (base + WREGION <= (long long)N);

    if (interior)
        run_warp<true >(gI, gU, gOut, base, N, alpha, a, thr, lane);
    else
        run_warp<false>(gI, gU, gOut, base, N, alpha, a, thr, lane);
}

extern "C" void kernel_launch(void* const* d_in, const int* in_sizes, int n_in,
                              void* d_out, int out_size)
{
    const float* I   = (const float*)d_in[0];
    const float* u   = (const float*)d_in[1];
    const float* tau = (const float*)d_in[2];
    const float* thr = (const float*)d_in[3];
    float* out = (float*)d_out;
    const int N = in_sizes[0];

    const int nWT = (N + WTILE - 1) / WTILE;        // 2341 warp tiles
    const int blocks = (nWT * 32 + THREADS - 1) / THREADS;  // 293

    neuron_kernel<<<blocks, THREADS>>>(I, u, tau, thr, out, N, nWT);
}

// round 9
// speedup vs baseline: 1.6403x; 1.5067x over previous
#include <cuda_runtime.h>

// RateBasedNeuron: N=2^23 neuron sim, warp-autonomous formulation (v7).
//  rate[t] = a*rate[t-1] + alpha*I[t]  (a = 1-1/tau, contractive)
//  p[t] = clip(rate/thr,0,1)*0.1 ; 3-state refractory DFA -> spikes.
//
// Each WARP owns an independent 2048-elem tile + 512-elem halo (a^512*50
// ~ 4e-12 << decision sensitivity; halo also warms the DFA). 20 serial
// segments of 128; per segment each lane owns one float4 (coalesced
// LDG/STG.128); scans over 32 lanes via shuffles, scalar carries between
// segments. No smem, no syncthreads.
//
// v7: (a) division replaced by multiply with precomputed rn(1/thr) — <=1 ulp
// perturbation of p, below the regrouping noise already validated;
// (b) IIR scan exploits constant per-round multipliers a^{4d} and per-lane
// a^{4*lane}: B-only scan, 7 shuffles/segment instead of 11;
// (c) WTILE=2048 doubles resident warps (grid was the occupancy limiter).

#define WSEG    128
#define NSEG    20
#define WREGION (WSEG * NSEG)        // 2560
#define WHALO   512
#define HSEG    (WHALO / WSEG)       // 4
#define WTILE   (WREGION - WHALO)    // 2048
#define PF      2
#define THREADS 256
#define FULLMASK 0xffffffffu

__device__ __forceinline__ unsigned dfa_spk(unsigned es, int* hb) {
    // greedy refractory fire over a 4-bit window: at most 2 fires
    unsigned b1 = es & (0u - es);
    unsigned r  = es & ~(b1 | (b1 << 1) | (b1 << 2));
    unsigned b2 = r & (0u - r);
    unsigned sk = b1 | b2;
    *hb = 31 - __clz(sk | 1u);                   // 0 when sk==0 (o<=0 then)
    return sk;
}

// compose byte-packed 3-state maps: apply g first, then f. h[i] = f[g[i]].
// __byte_perm selector = nibbles, so compress g's bytes into nibbles first.
__device__ __forceinline__ unsigned dfa_compose(unsigned f, unsigned g) {
    unsigned sel = (g & 3u) | ((g >> 4) & 0x30u) | ((g >> 8) & 0x300u);
    return __byte_perm(f, 0, sel);
}

template <bool INTERIOR>
__device__ __forceinline__ void run_warp(
    const float* __restrict__ gI, const float* __restrict__ gU,
    float* __restrict__ gOut, long long base, long long N,
    float alpha, float a, float rthr, int lane)
{
    // constant powers of a (round multipliers) and per-lane a^{4*lane}
    const float a2  = a * a;
    const float c1  = a2 * a2;       // a^4
    const float c2  = c1 * c1;       // a^8
    const float c4  = c2 * c2;       // a^16
    const float c8  = c4 * c4;       // a^32
    const float c16 = c8 * c8;       // a^64
    const float c32 = c16 * c16;     // a^128
    float aL = 1.0f, bp = c1;
    #pragma unroll
    for (int bit = 0; bit < 5; bit++) {
        if (lane & (1 << bit)) aL *= bp;
        bp *= bp;
    }

    float    rcar = 0.0f;   // IIR carry (rate entering current segment)
    unsigned scar = 0u;     // DFA carry state in {0,1,2}

    const float4* pI4 = (const float4*)(gI + base) + lane;
    const float4* pU4 = (const float4*)(gU + base) + lane;
    float4*       pO4 = (float4*)(gOut + base) + lane;

    float4 qb[PF], qu[PF];
    if (INTERIOR) {
        #pragma unroll
        for (int j = 0; j < PF; j++) { qb[j] = pI4[j * 32]; qu[j] = pU4[j * 32]; }
    }

    #pragma unroll 1
    for (int g = 0; g < NSEG / PF; g++) {
        #pragma unroll
        for (int j = 0; j < PF; j++) {
            const int seg = g * PF + j;
            float4 bv, uv;
            if (INTERIOR) {
                bv = qb[j]; uv = qu[j];
                if (g < NSEG / PF - 1) {           // prefetch seg+PF
                    qb[j] = pI4[(seg + PF) * 32];
                    qu[j] = pU4[(seg + PF) * 32];
                }
            } else {
                long long gg = base + (long long)seg * WSEG + lane * 4;
                bv.x = (gg + 0 >= 1 && gg + 0 < N) ? gI[gg + 0] : 0.0f;
                bv.y = (gg + 1 >= 1 && gg + 1 < N) ? gI[gg + 1] : 0.0f;
                bv.z = (gg + 2 >= 1 && gg + 2 < N) ? gI[gg + 2] : 0.0f;
                bv.w = (gg + 3 >= 1 && gg + 3 < N) ? gI[gg + 3] : 0.0f;
                uv.x = (gg + 0 >= 0 && gg + 0 < N) ? gU[gg + 0] : 1.0f;
                uv.y = (gg + 1 >= 0 && gg + 1 < N) ? gU[gg + 1] : 1.0f;
                uv.z = (gg + 2 >= 0 && gg + 2 < N) ? gU[gg + 2] : 1.0f;
                uv.w = (gg + 3 >= 0 && gg + 3 < N) ? gU[gg + 3] : 1.0f;
            }
            const float b0 = alpha * bv.x, b1 = alpha * bv.y;
            const float b2 = alpha * bv.z, b3 = alpha * bv.w;

            // ---- lane-local affine reduce (4 elems) ----
            float B = b0;
            B = fmaf(B, a, b1); B = fmaf(B, a, b2); B = fmaf(B, a, b3);

            // ---- warp inclusive scan of B with constant round multipliers -
            float Bi = B, Bu;
            Bu = __shfl_up_sync(FULLMASK, Bi, 1);  if (lane >= 1)  Bi = fmaf(Bu, c1,  Bi);
            Bu = __shfl_up_sync(FULLMASK, Bi, 2);  if (lane >= 2)  Bi = fmaf(Bu, c2,  Bi);
            Bu = __shfl_up_sync(FULLMASK, Bi, 4);  if (lane >= 4)  Bi = fmaf(Bu, c4,  Bi);
            Bu = __shfl_up_sync(FULLMASK, Bi, 8);  if (lane >= 8)  Bi = fmaf(Bu, c8,  Bi);
            Bu = __shfl_up_sync(FULLMASK, Bi, 16); if (lane >= 16) Bi = fmaf(Bu, c16, Bi);
            float Be  = __shfl_up_sync(FULLMASK, Bi, 1);
            if (lane == 0) Be = 0.0f;
            float B31 = __shfl_sync(FULLMASK, Bi, 31);
            float rin = fmaf(aL, rcar, Be);
            rcar = fmaf(c32, rcar, B31);

            // ---- rates -> p (mul by rn(1/thr)) -> eligibility bits --------
            float r = rin, q;
            unsigned e = 0;
            r = fmaf(a, r, b0);
            q = fminf(fmaxf(r * rthr, 0.0f), 1.0f) * 0.1f;
            e |= (uv.x < q ? 1u : 0u);
            r = fmaf(a, r, b1);
            q = fminf(fmaxf(r * rthr, 0.0f), 1.0f) * 0.1f;
            e |= (uv.y < q ? 2u : 0u);
            r = fmaf(a, r, b2);
            q = fminf(fmaxf(r * rthr, 0.0f), 1.0f) * 0.1f;
            e |= (uv.z < q ? 4u : 0u);
            r = fmaf(a, r, b3);
            q = fminf(fmaxf(r * rthr, 0.0f), 1.0f) * 0.1f;
            e |= (uv.w < q ? 8u : 0u);

            // ---- DFA over this lane's 4 steps, per incoming state --------
            int h0, h1, h2;
            unsigned sp0 = dfa_spk(e,        &h0);
            unsigned sp1 = dfa_spk(e & ~1u,  &h1);
            unsigned sp2 = dfa_spk(e & ~3u,  &h2);
            unsigned o0 = (h0 > 1) ? (unsigned)(h0 - 1) : 0u;  // hb+3-4
            unsigned o1 = (h1 > 1) ? (unsigned)(h1 - 1) : 0u;
            unsigned o2 = (h2 > 1) ? (unsigned)(h2 - 1) : 0u;
            unsigned fmap = o0 | (o1 << 8) | (o2 << 16);       // byte-packed

            // ---- warp scan of state maps (exact compose) -----------------
            unsigned Fi = fmap;
            #pragma unroll
            for (int d = 1; d < 32; d <<= 1) {
                unsigned Fu = __shfl_up_sync(FULLMASK, Fi, d);
                if (lane >= d) Fi = dfa_compose(Fi, Fu);   // Fu earlier
            }
            unsigned Fe  = __shfl_up_sync(FULLMASK, Fi, 1);
            unsigned F31 = __shfl_sync(FULLMASK, Fi, 31);
            unsigned sin = (lane == 0) ? scar : ((Fe >> (scar << 3)) & 3u);
            scar = (F31 >> (scar << 3)) & 3u;

            unsigned spikes = (sin == 0) ? sp0 : ((sin == 1) ? sp1 : sp2);

            // ---- store (skip halo segments) ------------------------------
            if (seg >= HSEG) {
                if (INTERIOR) {
                    float4 s4;
                    s4.x = (spikes & 1u) ? 1.0f : 0.0f;
                    s4.y = (spikes & 2u) ? 1.0f : 0.0f;
                    s4.z = (spikes & 4u) ? 1.0f : 0.0f;
                    s4.w = (spikes & 8u) ? 1.0f : 0.0f;
                    pO4[seg * 32] = s4;
                } else {
                    long long gg = base + (long long)seg * WSEG + lane * 4;
                    #pragma unroll
                    for (int t = 0; t < 4; t++)
                        if (gg + t >= 0 && gg + t < N)
                            gOut[gg + t] = ((spikes >> t) & 1u) ? 1.0f : 0.0f;
                }
            }
        }
    }
}

__global__ void __launch_bounds__(THREADS, 4)
neuron_kernel(const float* __restrict__ gI, const float* __restrict__ gU,
              const float* __restrict__ gTau, const float* __restrict__ gThr,
              float* __restrict__ gOut, int N, int nWT)
{
    const int gwarp = (int)((blockIdx.x * blockDim.x + threadIdx.x) >> 5);
    if (gwarp >= nWT) return;                       // whole-warp uniform exit
    const int lane = threadIdx.x & 31;

    const float alpha = __fdiv_rn(1.0f, gTau[0]);
    const float thr   = gThr[0];
    const float rthr  = __fdiv_rn(1.0f, thr);
    const float a     = 1.0f - alpha;

    const long long base = (long long)gwarp * WTILE - WHALO;
    const bool interior = (base >= 1) && (base + WREGION <= (long long)N);

    if (interior)
        run_warp<true >(gI, gU, gOut, base, N, alpha, a, rthr, lane);
    else
        run_warp<false>(gI, gU, gOut, base, N, alpha, a, rthr, lane);
}

extern "C" void kernel_launch(void* const* d_in, const int* in_sizes, int n_in,
                              void* d_out, int out_size)
{
    const float* I   = (const float*)d_in[0];
    const float* u   = (const float*)d_in[1];
    const float* tau = (const float*)d_in[2];
    const float* thr = (const float*)d_in[3];
    float* out = (float*)d_out;
    const int N = in_sizes[0];

    const int nWT = (N + WTILE - 1) / WTILE;        // 4096 warp tiles
    const int blocks = (nWT * 32 + THREADS - 1) / THREADS;  // 512

    neuron_kernel<<<blocks, THREADS>>>(I, u, tau, thr, out, N, nWT);
}

// round 10
// speedup vs baseline: 2.2150x; 1.3504x over previous
#include <cuda_runtime.h>

// RateBasedNeuron: N=2^23 neuron sim, warp-autonomous formulation (v8).
//  rate[t] = a*rate[t-1] + alpha*I[t]  (a = 1-1/tau, contractive)
//  p[t] = clip(rate/thr,0,1)*0.1 ; 3-state refractory DFA -> spikes.
//
// Each WARP owns an independent 2048-elem tile + 512-elem halo. 10 serial
// segments of 256; each lane owns 8 consecutive elems (two float4); IIR
// B-scan with constant round multipliers + DFA state-map scan via shuffles,
// scalar carries between segments.
//
// v8: (a) 8 elems/lane halves scan cost per element; (b) 3-state refractory
// DFA per-lane work (spikes for all 3 incoming states + transition map)
// replaced by a 256-entry shared LUT built once per block (uint2: spike
// masks + byte-packed map); (c) dropped provably-no-op fmax (r>=0).

#define WSEG    256
#define NSEG    10
#define WREGION (WSEG * NSEG)        // 2560
#define WHALO   512
#define HSEG    (WHALO / WSEG)       // 2
#define WTILE   (WREGION - WHALO)    // 2048
#define THREADS 256
#define FULLMASK 0xffffffffu

// compose byte-packed 3-state maps: apply g first, then f. h[i] = f[g[i]].
// __byte_perm selector = nibbles -> compress g's bytes into nibbles first.
__device__ __forceinline__ unsigned dfa_compose(unsigned f, unsigned g) {
    unsigned sel = (g & 3u) | ((g >> 4) & 0x30u) | ((g >> 8) & 0x300u);
    return __byte_perm(f, 0, sel);
}

template <bool INTERIOR>
__device__ __forceinline__ void run_warp(
    const float* __restrict__ gI, const float* __restrict__ gU,
    float* __restrict__ gOut, const uint2* __restrict__ tbl,
    long long base, long long N,
    float alpha, float a, float rthr, int lane)
{
    // powers of a: scan round multipliers (lane span = 8 elems)
    const float a2   = a * a;
    const float a4   = a2 * a2;
    const float c1   = a4 * a4;      // a^8
    const float c2   = c1 * c1;      // a^16
    const float c4   = c2 * c2;      // a^32
    const float c8   = c4 * c4;      // a^64
    const float c16  = c8 * c8;      // a^128
    const float cSeg = c16 * c16;    // a^256
    float aL = 1.0f, bp = c1;        // aL = a^{8*lane}
    #pragma unroll
    for (int bit = 0; bit < 5; bit++) {
        if (lane & (1 << bit)) aL *= bp;
        bp *= bp;
    }

    float    rcar = 0.0f;   // IIR carry entering current segment
    unsigned scar = 0u;     // DFA carry state in {0,1,2}

    const float4* pI4 = (const float4*)(gI + base);
    const float4* pU4 = (const float4*)(gU + base);
    float4*       pO4 = (float4*)(gOut + base);
    const int li = 2 * lane;

    float4 nb0, nb1, nu0, nu1;
    if (INTERIOR) {
        nb0 = pI4[li]; nb1 = pI4[li + 1];
        nu0 = pU4[li]; nu1 = pU4[li + 1];
    }

    #pragma unroll 1
    for (int seg = 0; seg < NSEG; seg++) {
        float4 cb0, cb1, cu0, cu1;
        if (INTERIOR) {
            cb0 = nb0; cb1 = nb1; cu0 = nu0; cu1 = nu1;
            if (seg + 1 < NSEG) {
                const int nx = (seg + 1) * (WSEG / 4) + li;
                nb0 = pI4[nx]; nb1 = pI4[nx + 1];
                nu0 = pU4[nx]; nu1 = pU4[nx + 1];
            }
        } else {
            long long gg = base + (long long)seg * WSEG + lane * 8;
            float* cb = (float*)&cb0;   // cb0,cb1 contiguous
            float* cu = (float*)&cu0;
            #pragma unroll
            for (int t = 0; t < 8; t++) {
                long long g = gg + t;
                ((float*)&cb0)[t & 3 | ((t >> 2) << 2)] = 0.0f; // placate idx
            }
            // simple guarded scalar fill
            float tmpb[8], tmpu[8];
            #pragma unroll
            for (int t = 0; t < 8; t++) {
                long long g = gg + t;
                tmpb[t] = (g >= 1 && g < N) ? gI[g] : 0.0f;
                tmpu[t] = (g >= 0 && g < N) ? gU[g] : 1.0f;
            }
            cb0 = make_float4(tmpb[0], tmpb[1], tmpb[2], tmpb[3]);
            cb1 = make_float4(tmpb[4], tmpb[5], tmpb[6], tmpb[7]);
            cu0 = make_float4(tmpu[0], tmpu[1], tmpu[2], tmpu[3]);
            cu1 = make_float4(tmpu[4], tmpu[5], tmpu[6], tmpu[7]);
        }

        const float b0 = alpha * cb0.x, b1 = alpha * cb0.y;
        const float b2 = alpha * cb0.z, b3 = alpha * cb0.w;
        const float b4 = alpha * cb1.x, b5 = alpha * cb1.y;
        const float b6 = alpha * cb1.z, b7 = alpha * cb1.w;

        // ---- lane-local affine reduce (8 elems) ----
        float B = b0;
        B = fmaf(B, a, b1); B = fmaf(B, a, b2); B = fmaf(B, a, b3);
        B = fmaf(B, a, b4); B = fmaf(B, a, b5); B = fmaf(B, a, b6);
        B = fmaf(B, a, b7);

        // ---- warp inclusive B-scan, constant round multipliers ----
        float Bi = B, Bu;
        Bu = __shfl_up_sync(FULLMASK, Bi, 1);  if (lane >= 1)  Bi = fmaf(Bu, c1,  Bi);
        Bu = __shfl_up_sync(FULLMASK, Bi, 2);  if (lane >= 2)  Bi = fmaf(Bu, c2,  Bi);
        Bu = __shfl_up_sync(FULLMASK, Bi, 4);  if (lane >= 4)  Bi = fmaf(Bu, c4,  Bi);
        Bu = __shfl_up_sync(FULLMASK, Bi, 8);  if (lane >= 8)  Bi = fmaf(Bu, c8,  Bi);
        Bu = __shfl_up_sync(FULLMASK, Bi, 16); if (lane >= 16) Bi = fmaf(Bu, c16, Bi);
        float Be  = __shfl_up_sync(FULLMASK, Bi, 1);
        if (lane == 0) Be = 0.0f;
        float B31 = __shfl_sync(FULLMASK, Bi, 31);
        float rin = fmaf(aL, rcar, Be);
        rcar = fmaf(cSeg, rcar, B31);

        // ---- rates -> p -> eligibility bits (r >= 0, fmax dropped) ----
        float r = rin, q;
        unsigned e = 0;
        r = fmaf(a, r, b0); q = fminf(r * rthr, 1.0f) * 0.1f; e |= (cu0.x < q ?   1u : 0u);
        r = fmaf(a, r, b1); q = fminf(r * rthr, 1.0f) * 0.1f; e |= (cu0.y < q ?   2u : 0u);
        r = fmaf(a, r, b2); q = fminf(r * rthr, 1.0f) * 0.1f; e |= (cu0.z < q ?   4u : 0u);
        r = fmaf(a, r, b3); q = fminf(r * rthr, 1.0f) * 0.1f; e |= (cu0.w < q ?   8u : 0u);
        r = fmaf(a, r, b4); q = fminf(r * rthr, 1.0f) * 0.1f; e |= (cu1.x < q ?  16u : 0u);
        r = fmaf(a, r, b5); q = fminf(r * rthr, 1.0f) * 0.1f; e |= (cu1.y < q ?  32u : 0u);
        r = fmaf(a, r, b6); q = fminf(r * rthr, 1.0f) * 0.1f; e |= (cu1.z < q ?  64u : 0u);
        r = fmaf(a, r, b7); q = fminf(r * rthr, 1.0f) * 0.1f; e |= (cu1.w < q ? 128u : 0u);

        // ---- DFA via LUT: spike masks (3 states) + byte-packed map ----
        uint2 en = tbl[e];

        // ---- warp scan of state maps (exact compose) ----
        unsigned Fi = en.y;
        #pragma unroll
        for (int d = 1; d < 32; d <<= 1) {
            unsigned Fu = __shfl_up_sync(FULLMASK, Fi, d);
            if (lane >= d) Fi = dfa_compose(Fi, Fu);   // Fu earlier
        }
        unsigned Fe  = __shfl_up_sync(FULLMASK, Fi, 1);
        unsigned F31 = __shfl_sync(FULLMASK, Fi, 31);
        unsigned sin = (lane == 0) ? scar : ((Fe >> (scar << 3)) & 3u);
        scar = (F31 >> (scar << 3)) & 3u;

        unsigned spikes = (en.x >> (sin << 3)) & 0xffu;

        // ---- store (skip halo segments) ----
        if (seg >= HSEG) {
            if (INTERIOR) {
                float4 s0, s1;
                s0.x = (spikes &   1u) ? 1.0f : 0.0f;
                s0.y = (spikes &   2u) ? 1.0f : 0.0f;
                s0.z = (spikes &   4u) ? 1.0f : 0.0f;
                s0.w = (spikes &   8u) ? 1.0f : 0.0f;
                s1.x = (spikes &  16u) ? 1.0f : 0.0f;
                s1.y = (spikes &  32u) ? 1.0f : 0.0f;
                s1.z = (spikes &  64u) ? 1.0f : 0.0f;
                s1.w = (spikes & 128u) ? 1.0f : 0.0f;
                const int ox = seg * (WSEG / 4) + li;
                pO4[ox] = s0; pO4[ox + 1] = s1;
            } else {
                long long gg = base + (long long)seg * WSEG + lane * 8;
                #pragma unroll
                for (int t = 0; t < 8; t++) {
                    long long g = gg + t;
                    if (g >= 0 && g < N)
                        gOut[g] = ((spikes >> t) & 1u) ? 1.0f : 0.0f;
                }
            }
        }
    }
}

__global__ void __launch_bounds__(THREADS, 4)
neuron_kernel(const float* __restrict__ gI, const float* __restrict__ gU,
              const float* __restrict__ gTau, const float* __restrict__ gThr,
              float* __restrict__ gOut, int N, int nWT)
{
    __shared__ uint2 tbl[256];

    // ---- build 8-step refractory-DFA LUT (one entry per thread) ----
    {
        const unsigned e = threadIdx.x;   // THREADS == 256
        unsigned spAll = 0, mAll = 0;
        #pragma unroll
        for (int s0 = 0; s0 < 3; s0++) {
            int s = s0;
            unsigned sp = 0;
            #pragma unroll
            for (int k = 0; k < 8; k++) {
                bool fire = (s == 0) && ((e >> k) & 1u);
                if (fire) sp |= 1u << k;
                s = fire ? 2 : (s > 0 ? s - 1 : 0);
            }
            spAll |= sp << (8 * s0);
            mAll  |= (unsigned)s << (8 * s0);
        }
        tbl[e] = make_uint2(spAll, mAll);
    }
    __syncthreads();

    const int gwarp = (int)((blockIdx.x * blockDim.x + threadIdx.x) >> 5);
    if (gwarp >= nWT) return;                       // whole-warp uniform exit
    const int lane = threadIdx.x & 31;

    const float alpha = __fdiv_rn(1.0f, gTau[0]);
    const float rthr  = __fdiv_rn(1.0f, gThr[0]);
    const float a     = 1.0f - alpha;

    const long long base = (long long)gwarp * WTILE - WHALO;
    const bool interior = (base >= 1) && (base + WREGION <= (long long)N);

    if (interior)
        run_warp<true >(gI, gU, gOut, tbl, base, N, alpha, a, rthr, lane);
    else
        run_warp<false>(gI, gU, gOut, tbl, base, N, alpha, a, rthr, lane);
}

extern "C" void kernel_launch(void* const* d_in, const int* in_sizes, int n_in,
                              void* d_out, int out_size)
{
    const float* I   = (const float*)d_in[0];
    const float* u   = (const float*)d_in[1];
    const float* tau = (const float*)d_in[2];
    const float* thr = (const float*)d_in[3];
    float* out = (float*)d_out;
    const int N = in_sizes[0];

    const int nWT = (N + WTILE - 1) / WTILE;        // 4096 warp tiles
    const int blocks = (nWT * 32 + THREADS - 1) / THREADS;  // 512

    neuron_kernel<<<blocks, THREADS>>>(I, u, tau, thr, out, N, nWT);
}